// round 1
// baseline (speedup 1.0000x reference)
#include <cuda_runtime.h>
#include <cstdint>

#define N_NODES 50000
#define E_EDGES 800000
#define DIN 128
#define DH 256
#define P_PAIRS 100000
#define M_PRED (2 * P_PAIRS)

// ---------------- scratch (static device allocations; no cudaMalloc) ----------
__device__ int   g_deg[N_NODES];
__device__ int   g_off[N_NODES + 1];
__device__ int   g_cursor[N_NODES];
__device__ int   g_sorted_src[E_EDGES];
__device__ int   g_bsum[64];
__device__ float g_agg[(size_t)N_NODES * DH];
__device__ float g_h1[(size_t)N_NODES * DH];
__device__ float g_h2[(size_t)N_NODES * DH];
__device__ float g_h3[(size_t)N_NODES * DH];
__device__ float g_z1[(size_t)M_PRED * DH];
__device__ float g_z2[(size_t)M_PRED * DH];

// ---------------- CSR build ---------------------------------------------------
__global__ void k_zero_deg() {
    int i = blockIdx.x * blockDim.x + threadIdx.x;
    if (i < N_NODES) g_deg[i] = 0;
}

__global__ void k_count(const int* __restrict__ dst) {
    int e = blockIdx.x * blockDim.x + threadIdx.x;
    if (e < E_EDGES) atomicAdd(&g_deg[dst[e]], 1);
}

__global__ void k_scan_block() {
    __shared__ int s[1024];
    int i = blockIdx.x * 1024 + threadIdx.x;
    int v = (i < N_NODES) ? g_deg[i] : 0;
    s[threadIdx.x] = v;
    __syncthreads();
    for (int ofs = 1; ofs < 1024; ofs <<= 1) {
        int t = (threadIdx.x >= ofs) ? s[threadIdx.x - ofs] : 0;
        __syncthreads();
        s[threadIdx.x] += t;
        __syncthreads();
    }
    if (i < N_NODES) g_off[i] = s[threadIdx.x] - v;  // exclusive
    if (threadIdx.x == 1023) g_bsum[blockIdx.x] = s[1023];
}

__global__ void k_scan_bsum(int nb) {
    if (threadIdx.x == 0 && blockIdx.x == 0) {
        int acc = 0;
        for (int b = 0; b < nb; b++) { int v = g_bsum[b]; g_bsum[b] = acc; acc += v; }
    }
}

__global__ void k_scan_add() {
    int i = blockIdx.x * blockDim.x + threadIdx.x;
    if (i < N_NODES) {
        int o = g_off[i] + g_bsum[i >> 10];
        g_off[i] = o;
        g_cursor[i] = o;
    }
    if (i == 0) g_off[N_NODES] = E_EDGES;
}

__global__ void k_scatter(const int* __restrict__ src, const int* __restrict__ dst) {
    int e = blockIdx.x * blockDim.x + threadIdx.x;
    if (e < E_EDGES) {
        int d = dst[e];
        int pos = atomicAdd(&g_cursor[d], 1);
        g_sorted_src[pos] = src[e];
    }
}

// ---------------- mean aggregation: one warp per node -------------------------
template <int D>
__global__ void k_aggregate(const float* __restrict__ h, float* __restrict__ agg) {
    int warp = (blockIdx.x * blockDim.x + threadIdx.x) >> 5;
    int lane = threadIdx.x & 31;
    if (warp >= N_NODES) return;
    int s0 = g_off[warp], s1 = g_off[warp + 1];
    constexpr int V = D / 128;  // float4 chunks per lane (1 or 2)
    float4 acc[V];
#pragma unroll
    for (int v = 0; v < V; v++) acc[v] = make_float4(0.f, 0.f, 0.f, 0.f);
    for (int e = s0; e < s1; e++) {
        int s = g_sorted_src[e];
        const float4* row = (const float4*)(h + (size_t)s * D);
#pragma unroll
        for (int v = 0; v < V; v++) {
            float4 x = row[lane + 32 * v];
            acc[v].x += x.x; acc[v].y += x.y; acc[v].z += x.z; acc[v].w += x.w;
        }
    }
    float inv = 1.0f / fmaxf((float)(s1 - s0), 1.0f);
    float4* o = (float4*)(agg + (size_t)warp * D);
#pragma unroll
    for (int v = 0; v < V; v++) {
        acc[v].x *= inv; acc[v].y *= inv; acc[v].z *= inv; acc[v].w *= inv;
        o[lane + 32 * v] = acc[v];
    }
}

// ---------------- fused dual-input SGEMM: out = A1@W1 + A2@W2 + b [+relu] -----
#define BM 64
#define BN 64
#define BK 16

__global__ void k_gemm_sage(const float* __restrict__ A1, int K1, const float* __restrict__ W1,
                            const float* __restrict__ A2, int K2, const float* __restrict__ W2,
                            const float* __restrict__ bias, float* __restrict__ out,
                            int M, int Nout, int relu) {
    __shared__ float sA[BK][BM + 4];
    __shared__ float sB[BK][BN];
    int tx = threadIdx.x & 15, ty = threadIdx.x >> 4;
    int m0 = blockIdx.y * BM, n0 = blockIdx.x * BN;
    float acc[4][4] = {};

    for (int pass = 0; pass < 2; pass++) {
        const float* A = pass ? A2 : A1;
        const float* W = pass ? W2 : W1;
        int K = pass ? K2 : K1;
        for (int k0 = 0; k0 < K; k0 += BK) {
            // A tile: 64 rows x 16 k, one float4 per thread
            {
                int r = threadIdx.x >> 2;
                int c = (threadIdx.x & 3) * 4;
                float4 v = make_float4(0.f, 0.f, 0.f, 0.f);
                int gr = m0 + r;
                if (gr < M) v = *(const float4*)(A + (size_t)gr * K + k0 + c);
                sA[c + 0][r] = v.x; sA[c + 1][r] = v.y;
                sA[c + 2][r] = v.z; sA[c + 3][r] = v.w;
            }
            // B tile: 16 k x 64 cols
            {
                int r = threadIdx.x >> 4;
                int c = (threadIdx.x & 15) * 4;
                float4 v = *(const float4*)(W + (size_t)(k0 + r) * Nout + n0 + c);
                *(float4*)&sB[r][c] = v;
            }
            __syncthreads();
#pragma unroll
            for (int kk = 0; kk < BK; kk++) {
                float a[4], b[4];
#pragma unroll
                for (int i = 0; i < 4; i++) a[i] = sA[kk][ty * 4 + i];
#pragma unroll
                for (int j = 0; j < 4; j++) b[j] = sB[kk][tx * 4 + j];
#pragma unroll
                for (int i = 0; i < 4; i++)
#pragma unroll
                    for (int j = 0; j < 4; j++) acc[i][j] += a[i] * b[j];
            }
            __syncthreads();
        }
    }
#pragma unroll
    for (int i = 0; i < 4; i++) {
        int gr = m0 + ty * 4 + i;
        if (gr >= M) continue;
#pragma unroll
        for (int j = 0; j < 4; j++) {
            int gc = n0 + tx * 4 + j;
            float v = acc[i][j] + bias[gc];
            if (relu) v = fmaxf(v, 0.f);
            out[(size_t)gr * Nout + gc] = v;
        }
    }
}

// ---------------- predictor GEMM1 with fused edge gather-product ---------------
// A[row,:] = h[src[row],:] * h[dst[row],:]   (elementwise), K = 256 fixed
__global__ void k_gemm_edge(const float* __restrict__ h,
                            const int* __restrict__ ps, const int* __restrict__ pd,
                            const int* __restrict__ ns, const int* __restrict__ nd,
                            const float* __restrict__ W, const float* __restrict__ bias,
                            float* __restrict__ out) {
    __shared__ float sA[BK][BM + 4];
    __shared__ float sB[BK][BN];
    int tx = threadIdx.x & 15, ty = threadIdx.x >> 4;
    int m0 = blockIdx.y * BM, n0 = blockIdx.x * BN;
    const int Nout = DH;
    float acc[4][4] = {};

    // per-thread A-load row indices (M_PRED is a multiple of 64, no guards)
    int r = threadIdx.x >> 2;
    int c = (threadIdx.x & 3) * 4;
    int gr = m0 + r;
    int s, d;
    if (gr < P_PAIRS) { s = ps[gr]; d = pd[gr]; }
    else              { s = ns[gr - P_PAIRS]; d = nd[gr - P_PAIRS]; }
    const float4* rs = (const float4*)(h + (size_t)s * DH);
    const float4* rd = (const float4*)(h + (size_t)d * DH);

    for (int k0 = 0; k0 < DH; k0 += BK) {
        {
            float4 a = rs[(k0 + c) >> 2];
            float4 b = rd[(k0 + c) >> 2];
            sA[c + 0][r] = a.x * b.x; sA[c + 1][r] = a.y * b.y;
            sA[c + 2][r] = a.z * b.z; sA[c + 3][r] = a.w * b.w;
        }
        {
            int br = threadIdx.x >> 4;
            int bc = (threadIdx.x & 15) * 4;
            float4 v = *(const float4*)(W + (size_t)(k0 + br) * Nout + n0 + bc);
            *(float4*)&sB[br][bc] = v;
        }
        __syncthreads();
#pragma unroll
        for (int kk = 0; kk < BK; kk++) {
            float a[4], b[4];
#pragma unroll
            for (int i = 0; i < 4; i++) a[i] = sA[kk][ty * 4 + i];
#pragma unroll
            for (int j = 0; j < 4; j++) b[j] = sB[kk][tx * 4 + j];
#pragma unroll
            for (int i = 0; i < 4; i++)
#pragma unroll
                for (int j = 0; j < 4; j++) acc[i][j] += a[i] * b[j];
        }
        __syncthreads();
    }
#pragma unroll
    for (int i = 0; i < 4; i++) {
        int orow = m0 + ty * 4 + i;
#pragma unroll
        for (int j = 0; j < 4; j++) {
            int gc = n0 + tx * 4 + j;
            float v = acc[i][j] + bias[gc];
            out[(size_t)orow * Nout + gc] = fmaxf(v, 0.f);
        }
    }
}

// ---------------- final 256 -> 1 dot: one warp per row -------------------------
__global__ void k_final(const float* __restrict__ z, const float* __restrict__ Wp3,
                        const float* __restrict__ bp3, float* __restrict__ out) {
    int warp = (blockIdx.x * blockDim.x + threadIdx.x) >> 5;
    int lane = threadIdx.x & 31;
    if (warp >= M_PRED) return;
    const float4* row = (const float4*)(z + (size_t)warp * DH);
    const float4* w = (const float4*)Wp3;
    float sum = 0.f;
#pragma unroll
    for (int v = 0; v < 2; v++) {
        float4 a = row[lane + 32 * v];
        float4 b = w[lane + 32 * v];
        sum += a.x * b.x + a.y * b.y + a.z * b.z + a.w * b.w;
    }
#pragma unroll
    for (int o = 16; o > 0; o >>= 1) sum += __shfl_xor_sync(0xFFFFFFFFu, sum, o);
    if (lane == 0) out[warp] = sum + bp3[0];
}

// ---------------- host orchestration ------------------------------------------
extern "C" void kernel_launch(void* const* d_in, const int* in_sizes, int n_in,
                              void* d_out, int out_size) {
    const float* x        = (const float*)d_in[0];
    const int*   edge_src = (const int*)d_in[1];
    const int*   edge_dst = (const int*)d_in[2];
    const int*   pos_src  = (const int*)d_in[3];
    const int*   pos_dst  = (const int*)d_in[4];
    const int*   neg_src  = (const int*)d_in[5];
    const int*   neg_dst  = (const int*)d_in[6];
    const float* Ws0 = (const float*)d_in[7];
    const float* Wn0 = (const float*)d_in[8];
    const float* b0  = (const float*)d_in[9];
    const float* Ws1 = (const float*)d_in[10];
    const float* Wn1 = (const float*)d_in[11];
    const float* b1  = (const float*)d_in[12];
    const float* Ws2 = (const float*)d_in[13];
    const float* Wn2 = (const float*)d_in[14];
    const float* b2  = (const float*)d_in[15];
    const float* Wp1 = (const float*)d_in[16];
    const float* bp1 = (const float*)d_in[17];
    const float* Wp2 = (const float*)d_in[18];
    const float* bp2 = (const float*)d_in[19];
    const float* Wp3 = (const float*)d_in[20];
    const float* bp3 = (const float*)d_in[21];
    float* out = (float*)d_out;

    float *agg, *h1, *h2, *h3, *z1, *z2;
    cudaGetSymbolAddress((void**)&agg, g_agg);
    cudaGetSymbolAddress((void**)&h1, g_h1);
    cudaGetSymbolAddress((void**)&h2, g_h2);
    cudaGetSymbolAddress((void**)&h3, g_h3);
    cudaGetSymbolAddress((void**)&z1, g_z1);
    cudaGetSymbolAddress((void**)&z2, g_z2);

    // CSR build (counting sort by dst)
    k_zero_deg<<<(N_NODES + 255) / 256, 256>>>();
    k_count<<<(E_EDGES + 255) / 256, 256>>>(edge_dst);
    int nb = (N_NODES + 1023) / 1024;
    k_scan_block<<<nb, 1024>>>();
    k_scan_bsum<<<1, 32>>>(nb);
    k_scan_add<<<(N_NODES + 255) / 256, 256>>>();
    k_scatter<<<(E_EDGES + 255) / 256, 256>>>(edge_src, edge_dst);

    const int AGG_BLOCKS = (N_NODES * 32 + 255) / 256;
    dim3 gemm_grid_node(DH / BN, (N_NODES + BM - 1) / BM);
    dim3 gemm_grid_pred(DH / BN, M_PRED / BM);

    // Layer 0: K=128
    k_aggregate<DIN><<<AGG_BLOCKS, 256>>>(x, agg);
    k_gemm_sage<<<gemm_grid_node, 256>>>(x, DIN, Ws0, agg, DIN, Wn0, b0, h1, N_NODES, DH, 1);
    // Layer 1
    k_aggregate<DH><<<AGG_BLOCKS, 256>>>(h1, agg);
    k_gemm_sage<<<gemm_grid_node, 256>>>(h1, DH, Ws1, agg, DH, Wn1, b1, h2, N_NODES, DH, 1);
    // Layer 2 (no relu)
    k_aggregate<DH><<<AGG_BLOCKS, 256>>>(h2, agg);
    k_gemm_sage<<<gemm_grid_node, 256>>>(h2, DH, Ws2, agg, DH, Wn2, b2, h3, N_NODES, DH, 0);

    // Predictor
    k_gemm_edge<<<gemm_grid_pred, 256>>>(h3, pos_src, pos_dst, neg_src, neg_dst, Wp1, bp1, z1);
    k_gemm_sage<<<gemm_grid_pred, 256>>>(z1, DH, Wp2, z1, 0, Wp2, bp2, z2, M_PRED, DH, 1);
    k_final<<<(M_PRED * 32 + 255) / 256, 256>>>(z2, Wp3, bp3, out);
}

// round 4
// speedup vs baseline: 2.2629x; 2.2629x over previous
#include <cuda_runtime.h>
#include <cuda_bf16.h>
#include <cstdint>

#define N_NODES 50000
#define E_EDGES 800000
#define DIN 128
#define DH 256
#define P_PAIRS 100000
#define M_PRED (2 * P_PAIRS)

// ================= helpers =====================================================
__device__ __forceinline__ uint32_t smem_u32(const void* p) {
    uint32_t a;
    asm("{ .reg .u64 t; cvta.to.shared.u64 t, %1; cvt.u32.u64 %0, t; }" : "=r"(a) : "l"(p));
    return a;
}
__device__ __forceinline__ uint32_t lds_u32(uint32_t a) {
    uint32_t v;
    asm volatile("ld.shared.b32 %0, [%1];" : "=r"(v) : "r"(a));
    return v;
}
__device__ __forceinline__ void cp16(uint32_t dst, const void* src, uint32_t sz) {
    asm volatile("cp.async.cg.shared.global [%0], [%1], 16, %2;"
                 :: "r"(dst), "l"(src), "r"(sz) : "memory");
}
__device__ __forceinline__ void cp_commit() {
    asm volatile("cp.async.commit_group;" ::: "memory");
}
#define CP_WAIT(n) asm volatile("cp.async.wait_group %0;" :: "n"(n) : "memory")

__device__ __forceinline__ void mma_bf16(float* d, const uint32_t* a, const uint32_t* b) {
    asm volatile(
        "mma.sync.aligned.m16n8k16.row.col.f32.bf16.bf16.f32 "
        "{%0,%1,%2,%3}, {%4,%5,%6,%7}, {%8,%9}, {%0,%1,%2,%3};"
        : "+f"(d[0]), "+f"(d[1]), "+f"(d[2]), "+f"(d[3])
        : "r"(a[0]), "r"(a[1]), "r"(a[2]), "r"(a[3]), "r"(b[0]), "r"(b[1]));
}

// split fp32 -> (hi, lo) bf16
__device__ __forceinline__ void split1(float v, uint16_t& h, uint16_t& l) {
    __nv_bfloat16 hb = __float2bfloat16_rn(v);
    float r = v - __bfloat162float(hb);
    __nv_bfloat16 lb = __float2bfloat16_rn(r);
    h = __bfloat16_as_ushort(hb);
    l = __bfloat16_as_ushort(lb);
}
__device__ __forceinline__ void split2(float v0, float v1, uint32_t& hi, uint32_t& lo) {
    uint16_t h0, l0, h1, l1;
    split1(v0, h0, l0); split1(v1, h1, l1);
    hi = (uint32_t)h0 | ((uint32_t)h1 << 16);
    lo = (uint32_t)l0 | ((uint32_t)l1 << 16);
}
__device__ __forceinline__ void split8(const float* v, uint4& hi, uint4& lo) {
    uint32_t h[4], l[4];
#pragma unroll
    for (int i = 0; i < 4; i++) split2(v[2 * i], v[2 * i + 1], h[i], l[i]);
    hi = make_uint4(h[0], h[1], h[2], h[3]);
    lo = make_uint4(l[0], l[1], l[2], l[3]);
}
// unpack 8 split values -> fp32 (exact: bf16 -> fp32 via shift)
__device__ __forceinline__ void unpack8(uint4 hi, uint4 lo, float* v) {
    uint32_t hw[4] = {hi.x, hi.y, hi.z, hi.w};
    uint32_t lw[4] = {lo.x, lo.y, lo.z, lo.w};
#pragma unroll
    for (int i = 0; i < 4; i++) {
        v[2 * i]     = __uint_as_float(hw[i] << 16) + __uint_as_float(lw[i] << 16);
        v[2 * i + 1] = __uint_as_float(hw[i] & 0xffff0000u) + __uint_as_float(lw[i] & 0xffff0000u);
    }
}

// Split tensor layout: row r of a [M, K] tensor occupies K*4 bytes:
//   (K/32) blocks of 128B; block = [4 x 16B hi chunks (k=0..31) | 4 x 16B lo chunks]
#define ROWB(K) ((K) * 4)

// ================= scratch =====================================================
__device__ int g_deg[N_NODES];
__device__ int g_off[N_NODES + 1];
__device__ int g_cursor[N_NODES];
__device__ int g_sorted_src[E_EDGES];
__device__ int g_bsum[64];
__device__ __align__(16) uint8_t g_xs[(size_t)N_NODES * DIN * 4];
__device__ __align__(16) uint8_t g_agg[(size_t)N_NODES * DH * 4];
__device__ __align__(16) uint8_t g_h1[(size_t)N_NODES * DH * 4];
__device__ __align__(16) uint8_t g_h2[(size_t)N_NODES * DH * 4];
__device__ __align__(16) uint8_t g_h3[(size_t)N_NODES * DH * 4];
__device__ __align__(16) uint8_t g_z1[(size_t)M_PRED * DH * 4];
__device__ __align__(16) uint8_t g_z2[(size_t)M_PRED * DH * 4];
__device__ __align__(16) uint8_t g_wt[1835008];

#define WT_WS0 0
#define WT_WN0 131072
#define WT_WS1 262144
#define WT_WN1 524288
#define WT_WS2 786432
#define WT_WN2 1048576
#define WT_WP1 1310720
#define WT_WP2 1572864

// ================= CSR build ===================================================
__global__ void k_zero_deg() {
    int i = blockIdx.x * blockDim.x + threadIdx.x;
    if (i < N_NODES) g_deg[i] = 0;
}
__global__ void k_count(const int* __restrict__ dst) {
    int e = blockIdx.x * blockDim.x + threadIdx.x;
    if (e < E_EDGES) atomicAdd(&g_deg[dst[e]], 1);
}
__global__ void k_scan_block() {
    __shared__ int s[1024];
    int i = blockIdx.x * 1024 + threadIdx.x;
    int v = (i < N_NODES) ? g_deg[i] : 0;
    s[threadIdx.x] = v;
    __syncthreads();
    for (int ofs = 1; ofs < 1024; ofs <<= 1) {
        int t = (threadIdx.x >= ofs) ? s[threadIdx.x - ofs] : 0;
        __syncthreads();
        s[threadIdx.x] += t;
        __syncthreads();
    }
    if (i < N_NODES) g_off[i] = s[threadIdx.x] - v;
    if (threadIdx.x == 1023) g_bsum[blockIdx.x] = s[1023];
}
__global__ void k_scan_bsum(int nb) {
    if (threadIdx.x == 0 && blockIdx.x == 0) {
        int acc = 0;
        for (int b = 0; b < nb; b++) { int v = g_bsum[b]; g_bsum[b] = acc; acc += v; }
    }
}
__global__ void k_scan_add() {
    int i = blockIdx.x * blockDim.x + threadIdx.x;
    if (i < N_NODES) {
        int o = g_off[i] + g_bsum[i >> 10];
        g_off[i] = o;
        g_cursor[i] = o;
    }
    if (i == 0) g_off[N_NODES] = E_EDGES;
}
__global__ void k_scatter(const int* __restrict__ src, const int* __restrict__ dst) {
    int e = blockIdx.x * blockDim.x + threadIdx.x;
    if (e < E_EDGES) {
        int d = dst[e];
        int pos = atomicAdd(&g_cursor[d], 1);
        g_sorted_src[pos] = src[e];
    }
}

// ================= prep: split fp32 tensors into hi/lo bf16 layout =============
// x: [M, K] fp32 row-major -> split layout. One thread per 8 elements.
__global__ void k_split_act(const float* __restrict__ x, uint8_t* __restrict__ out,
                            int M, int K) {
    int units = K >> 3;
    int i = blockIdx.x * blockDim.x + threadIdx.x;
    if (i >= M * units) return;
    int row = i / units, u = i % units;
    const float* src = x + (size_t)row * K + u * 8;
    float v[8];
#pragma unroll
    for (int j = 0; j < 8; j++) v[j] = src[j];
    uint4 hi, lo;
    split8(v, hi, lo);
    uint8_t* base = out + (size_t)row * ROWB(K) + (u >> 2) * 128 + (u & 3) * 16;
    *(uint4*)base = hi;
    *(uint4*)(base + 64) = lo;
}

// W: [K, N] fp32 -> split layout of W^T i.e. [N, K]. One thread per element.
__global__ void k_prep_w(const float* __restrict__ W, uint8_t* __restrict__ out,
                         int K, int N) {
    int i = blockIdx.x * blockDim.x + threadIdx.x;
    if (i >= K * N) return;
    int n = i / K, k = i % K;
    float v = W[(size_t)k * N + n];
    uint16_t h, l;
    split1(v, h, l);
    uint8_t* base = out + (size_t)n * ROWB(K) + (k >> 5) * 128 + ((k >> 3) & 3) * 16 + (k & 7) * 2;
    *(uint16_t*)base = h;
    *(uint16_t*)(base + 64) = l;
}

// ================= mean aggregation (split in, split out) ======================
template <int D>
__global__ void k_aggregate(const uint8_t* __restrict__ h, uint8_t* __restrict__ agg) {
    int warp = (blockIdx.x * blockDim.x + threadIdx.x) >> 5;
    int lane = threadIdx.x & 31;
    if (warp >= N_NODES) return;
    constexpr int UNITS = D / 8;
    int s0 = g_off[warp], s1 = g_off[warp + 1];
    if (lane >= UNITS) return;
    size_t uoff = (size_t)(lane >> 2) * 128 + (lane & 3) * 16;
    float acc[8];
#pragma unroll
    for (int j = 0; j < 8; j++) acc[j] = 0.f;
    for (int e = s0; e < s1; e++) {
        int s = g_sorted_src[e];
        const uint8_t* p = h + (size_t)s * ROWB(D) + uoff;
        uint4 hi = *(const uint4*)p;
        uint4 lo = *(const uint4*)(p + 64);
        float v[8];
        unpack8(hi, lo, v);
#pragma unroll
        for (int j = 0; j < 8; j++) acc[j] += v[j];
    }
    float inv = 1.0f / fmaxf((float)(s1 - s0), 1.0f);
#pragma unroll
    for (int j = 0; j < 8; j++) acc[j] *= inv;
    uint4 hi, lo;
    split8(acc, hi, lo);
    uint8_t* o = agg + (size_t)warp * ROWB(D) + uoff;
    *(uint4*)o = hi;
    *(uint4*)(o + 64) = lo;
}

// ================= split-bf16 3-MMA GEMM =======================================
// out[M,256](split) = A1[M,K1]@B1' + A2[M,K2]@B2' + bias, optional relu.
// A*, B* in split layout; B* is [256, K] (transposed weights). CTA tile 128x128.
#define ASTG 16384
#define STAGE 32768

struct GemmCtx {
    uint32_t sbase;
    int m0, n0;
    int wm, wn, gid, ctg;
};

__device__ __forceinline__ void gemm_compute(const GemmCtx& g, int buf, float acc[2][8][4]) {
    uint32_t aB = g.sbase + buf * STAGE;
    uint32_t bB = aB + ASTG;
    int arow0 = g.wm * 32 + g.gid;
    int brow0 = g.wn * 64 + g.gid;
    uint32_t cb = (uint32_t)g.ctg * 4;
#pragma unroll
    for (int ks = 0; ks < 2; ks++) {
        uint32_t ahi[2][4], alo[2][4];
#pragma unroll
        for (int mt = 0; mt < 2; mt++) {
            int r0 = arow0 + mt * 16, r1 = r0 + 8;
            uint32_t b0 = aB + r0 * 128, b1 = aB + r1 * 128;
            int c0 = 2 * ks, c1 = 2 * ks + 1;
            ahi[mt][0] = lds_u32(b0 + (uint32_t)((c0 ^ (r0 & 7)) << 4) + cb);
            ahi[mt][1] = lds_u32(b1 + (uint32_t)((c0 ^ (r1 & 7)) << 4) + cb);
            ahi[mt][2] = lds_u32(b0 + (uint32_t)((c1 ^ (r0 & 7)) << 4) + cb);
            ahi[mt][3] = lds_u32(b1 + (uint32_t)((c1 ^ (r1 & 7)) << 4) + cb);
            alo[mt][0] = lds_u32(b0 + (uint32_t)(((c0 + 4) ^ (r0 & 7)) << 4) + cb);
            alo[mt][1] = lds_u32(b1 + (uint32_t)(((c0 + 4) ^ (r1 & 7)) << 4) + cb);
            alo[mt][2] = lds_u32(b0 + (uint32_t)(((c1 + 4) ^ (r0 & 7)) << 4) + cb);
            alo[mt][3] = lds_u32(b1 + (uint32_t)(((c1 + 4) ^ (r1 & 7)) << 4) + cb);
        }
#pragma unroll
        for (int nt = 0; nt < 8; nt++) {
            int r = brow0 + nt * 8;
            uint32_t bb = bB + r * 128;
            int rs = r & 7;
            uint32_t bhi[2], blo[2];
            bhi[0] = lds_u32(bb + (uint32_t)(((2 * ks) ^ rs) << 4) + cb);
            bhi[1] = lds_u32(bb + (uint32_t)(((2 * ks + 1) ^ rs) << 4) + cb);
            blo[0] = lds_u32(bb + (uint32_t)(((2 * ks + 4) ^ rs) << 4) + cb);
            blo[1] = lds_u32(bb + (uint32_t)(((2 * ks + 5) ^ rs) << 4) + cb);
#pragma unroll
            for (int mt = 0; mt < 2; mt++) {
                mma_bf16(acc[mt][nt], ahi[mt], bhi);
                mma_bf16(acc[mt][nt], alo[mt], bhi);
                mma_bf16(acc[mt][nt], ahi[mt], blo);
            }
        }
    }
}

__device__ __forceinline__ void gemm_epilogue(const GemmCtx& g, float acc[2][8][4],
                                              const float* __restrict__ bias,
                                              uint8_t* __restrict__ out, int M, int relu) {
#pragma unroll
    for (int mt = 0; mt < 2; mt++) {
        int r0 = g.m0 + g.wm * 32 + mt * 16 + g.gid;
#pragma unroll
        for (int nt = 0; nt < 8; nt++) {
            int col = g.n0 + g.wn * 64 + nt * 8 + g.ctg * 2;
            float bx = __ldg(&bias[col]), by = __ldg(&bias[col + 1]);
            size_t coff = (size_t)(col >> 5) * 128 + ((col >> 3) & 3) * 16 + (col & 7) * 2;
#pragma unroll
            for (int rr = 0; rr < 2; rr++) {
                int r = r0 + rr * 8;
                if (r >= M) continue;
                float vx = acc[mt][nt][2 * rr] + bx, vy = acc[mt][nt][2 * rr + 1] + by;
                if (relu) { vx = fmaxf(vx, 0.f); vy = fmaxf(vy, 0.f); }
                uint32_t hi, lo;
                split2(vx, vy, hi, lo);
                uint8_t* base = out + (size_t)r * ROWB(DH) + coff;
                *(uint32_t*)base = hi;
                *(uint32_t*)(base + 64) = lo;
            }
        }
    }
}

__global__ __launch_bounds__(256, 2) void k_gemm_mma(
    const uint8_t* __restrict__ A1, int K1, const uint8_t* __restrict__ B1,
    const uint8_t* __restrict__ A2, int K2, const uint8_t* __restrict__ B2,
    const float* __restrict__ bias, uint8_t* __restrict__ out, int M, int relu) {
    extern __shared__ char smem[];
    int tid = threadIdx.x;
    GemmCtx g;
    g.sbase = smem_u32(smem);
    g.m0 = blockIdx.y * 128; g.n0 = blockIdx.x * 128;
    int wid = tid >> 5, lane = tid & 31;
    g.wm = wid >> 1; g.wn = wid & 1; g.gid = lane >> 2; g.ctg = lane & 3;

    int nc1 = K1 >> 5;
    int nch = nc1 + (K2 >> 5);
    int srow = tid >> 3, su = tid & 7;

    auto issue = [&](int c) {
        int buf = c & 1;
        const uint8_t* A; const uint8_t* B; int K, kc;
        if (c < nc1) { A = A1; B = B1; K = K1; kc = c; }
        else         { A = A2; B = B2; K = K2; kc = c - nc1; }
        uint32_t aB = g.sbase + buf * STAGE;
        uint32_t bB = aB + ASTG;
#pragma unroll
        for (int q = 0; q < 4; q++) {
            int row = srow + q * 32;
            uint32_t dst = aB + row * 128 + (uint32_t)((su ^ (row & 7)) << 4);
            int gr = g.m0 + row;
            uint32_t sz = (gr < M) ? 16u : 0u;
            const uint8_t* src = A + (size_t)(gr < M ? gr : (M - 1)) * ROWB(K) + kc * 128 + su * 16;
            cp16(dst, src, sz);
        }
#pragma unroll
        for (int q = 0; q < 4; q++) {
            int row = srow + q * 32;
            uint32_t dst = bB + row * 128 + (uint32_t)((su ^ (row & 7)) << 4);
            const uint8_t* src = B + (size_t)(g.n0 + row) * ROWB(K) + kc * 128 + su * 16;
            cp16(dst, src, 16u);
        }
        cp_commit();
    };

    issue(0);
    if (nch > 1) issue(1);

    float acc[2][8][4];
#pragma unroll
    for (int mt = 0; mt < 2; mt++)
#pragma unroll
        for (int nt = 0; nt < 8; nt++)
#pragma unroll
            for (int j = 0; j < 4; j++) acc[mt][nt][j] = 0.f;

    for (int c = 0; c < nch; c++) {
        if (c + 1 < nch) { CP_WAIT(1); } else { CP_WAIT(0); }
        __syncthreads();
        gemm_compute(g, c & 1, acc);
        __syncthreads();
        if (c + 2 < nch) issue(c + 2);
    }
    gemm_epilogue(g, acc, bias, out, M, relu);
}

// ================= predictor GEMM1: A = h[src]*h[dst] built on the fly =========
__global__ __launch_bounds__(256, 2) void k_gemm_edge_mma(
    const uint8_t* __restrict__ h,
    const int* __restrict__ ps, const int* __restrict__ pd,
    const int* __restrict__ ns, const int* __restrict__ nd,
    const uint8_t* __restrict__ B, const float* __restrict__ bias,
    uint8_t* __restrict__ out) {
    extern __shared__ char smem[];
    int tid = threadIdx.x;
    GemmCtx g;
    g.sbase = smem_u32(smem);
    g.m0 = blockIdx.y * 128; g.n0 = blockIdx.x * 128;
    int wid = tid >> 5, lane = tid & 31;
    g.wm = wid >> 1; g.wn = wid & 1; g.gid = lane >> 2; g.ctg = lane & 3;

    const int nch = DH >> 5;  // 8
    int srow = tid >> 3, su = tid & 7;

    int r = tid >> 1, half = tid & 1;
    int gr = g.m0 + r;
    bool valid = gr < M_PRED;
    int s = 0, d = 0;
    if (valid) {
        if (gr < P_PAIRS) { s = ps[gr]; d = pd[gr]; }
        else              { s = ns[gr - P_PAIRS]; d = nd[gr - P_PAIRS]; }
    }
    const uint8_t* rowS = h + (size_t)s * ROWB(DH);
    const uint8_t* rowD = h + (size_t)d * ROWB(DH);

    auto stage_a = [&](int c) {
        int buf = c & 1;
        uint32_t aB = g.sbase + buf * STAGE;
#pragma unroll
        for (int ci = 0; ci < 2; ci++) {
            int ch = half * 2 + ci;  // hi chunk index 0..3
            float v[8];
            if (valid) {
                const uint8_t* pS = rowS + c * 128 + ch * 16;
                const uint8_t* pD = rowD + c * 128 + ch * 16;
                uint4 shi = *(const uint4*)pS, slo = *(const uint4*)(pS + 64);
                uint4 dhi = *(const uint4*)pD, dlo = *(const uint4*)(pD + 64);
                float sv[8], dv[8];
                unpack8(shi, slo, sv);
                unpack8(dhi, dlo, dv);
#pragma unroll
                for (int j = 0; j < 8; j++) v[j] = sv[j] * dv[j];
            } else {
#pragma unroll
                for (int j = 0; j < 8; j++) v[j] = 0.f;
            }
            uint4 hi, lo;
            split8(v, hi, lo);
            uint32_t dhiA = aB + r * 128 + (uint32_t)((ch ^ (r & 7)) << 4);
            uint32_t dloA = aB + r * 128 + (uint32_t)(((ch + 4) ^ (r & 7)) << 4);
            asm volatile("st.shared.v4.b32 [%0], {%1,%2,%3,%4};"
                         :: "r"(dhiA), "r"(hi.x), "r"(hi.y), "r"(hi.z), "r"(hi.w) : "memory");
            asm volatile("st.shared.v4.b32 [%0], {%1,%2,%3,%4};"
                         :: "r"(dloA), "r"(lo.x), "r"(lo.y), "r"(lo.z), "r"(lo.w) : "memory");
        }
    };
    auto issue_b = [&](int c) {
        int buf = c & 1;
        uint32_t bB = g.sbase + buf * STAGE + ASTG;
#pragma unroll
        for (int q = 0; q < 4; q++) {
            int row = srow + q * 32;
            uint32_t dst = bB + row * 128 + (uint32_t)((su ^ (row & 7)) << 4);
            const uint8_t* src = B + (size_t)(g.n0 + row) * ROWB(DH) + c * 128 + su * 16;
            cp16(dst, src, 16u);
        }
        cp_commit();
    };

    stage_a(0); issue_b(0);
    stage_a(1); issue_b(1);

    float acc[2][8][4];
#pragma unroll
    for (int mt = 0; mt < 2; mt++)
#pragma unroll
        for (int nt = 0; nt < 8; nt++)
#pragma unroll
            for (int j = 0; j < 4; j++) acc[mt][nt][j] = 0.f;

    for (int c = 0; c < nch; c++) {
        if (c + 1 < nch) { CP_WAIT(1); } else { CP_WAIT(0); }
        __syncthreads();
        gemm_compute(g, c & 1, acc);
        __syncthreads();
        if (c + 2 < nch) { stage_a(c + 2); issue_b(c + 2); }
    }
    gemm_epilogue(g, acc, bias, out, M_PRED, 1);
}

// ================= final 256 -> 1 dot (split input) ============================
__global__ void k_final(const uint8_t* __restrict__ z, const float* __restrict__ Wp3,
                        const float* __restrict__ bp3, float* __restrict__ out) {
    int warp = (blockIdx.x * blockDim.x + threadIdx.x) >> 5;
    int lane = threadIdx.x & 31;
    if (warp >= M_PRED) return;
    const uint8_t* p = z + (size_t)warp * ROWB(DH) + (size_t)(lane >> 2) * 128 + (lane & 3) * 16;
    uint4 hi = *(const uint4*)p;
    uint4 lo = *(const uint4*)(p + 64);
    float v[8];
    unpack8(hi, lo, v);
    const float* w = Wp3 + lane * 8;
    float sum = 0.f;
#pragma unroll
    for (int j = 0; j < 8; j++) sum += v[j] * __ldg(&w[j]);
#pragma unroll
    for (int o = 16; o > 0; o >>= 1) sum += __shfl_xor_sync(0xFFFFFFFFu, sum, o);
    if (lane == 0) out[warp] = sum + bp3[0];
}

// ================= host orchestration ==========================================
extern "C" void kernel_launch(void* const* d_in, const int* in_sizes, int n_in,
                              void* d_out, int out_size) {
    const float* x        = (const float*)d_in[0];
    const int*   edge_src = (const int*)d_in[1];
    const int*   edge_dst = (const int*)d_in[2];
    const int*   pos_src  = (const int*)d_in[3];
    const int*   pos_dst  = (const int*)d_in[4];
    const int*   neg_src  = (const int*)d_in[5];
    const int*   neg_dst  = (const int*)d_in[6];
    const float* Ws0 = (const float*)d_in[7];
    const float* Wn0 = (const float*)d_in[8];
    const float* b0  = (const float*)d_in[9];
    const float* Ws1 = (const float*)d_in[10];
    const float* Wn1 = (const float*)d_in[11];
    const float* b1  = (const float*)d_in[12];
    const float* Ws2 = (const float*)d_in[13];
    const float* Wn2 = (const float*)d_in[14];
    const float* b2  = (const float*)d_in[15];
    const float* Wp1 = (const float*)d_in[16];
    const float* bp1 = (const float*)d_in[17];
    const float* Wp2 = (const float*)d_in[18];
    const float* bp2 = (const float*)d_in[19];
    const float* Wp3 = (const float*)d_in[20];
    const float* bp3 = (const float*)d_in[21];
    float* out = (float*)d_out;

    uint8_t *xs, *agg, *h1, *h2, *h3, *z1, *z2, *wt;
    cudaGetSymbolAddress((void**)&xs, g_xs);
    cudaGetSymbolAddress((void**)&agg, g_agg);
    cudaGetSymbolAddress((void**)&h1, g_h1);
    cudaGetSymbolAddress((void**)&h2, g_h2);
    cudaGetSymbolAddress((void**)&h3, g_h3);
    cudaGetSymbolAddress((void**)&z1, g_z1);
    cudaGetSymbolAddress((void**)&z2, g_z2);
    cudaGetSymbolAddress((void**)&wt, g_wt);

    cudaFuncSetAttribute(k_gemm_mma, cudaFuncAttributeMaxDynamicSharedMemorySize, 2 * STAGE);
    cudaFuncSetAttribute(k_gemm_edge_mma, cudaFuncAttributeMaxDynamicSharedMemorySize, 2 * STAGE);

    // weight/activation prep
    k_prep_w<<<(DIN * DH + 255) / 256, 256>>>(Ws0, wt + WT_WS0, DIN, DH);
    k_prep_w<<<(DIN * DH + 255) / 256, 256>>>(Wn0, wt + WT_WN0, DIN, DH);
    k_prep_w<<<(DH * DH + 255) / 256, 256>>>(Ws1, wt + WT_WS1, DH, DH);
    k_prep_w<<<(DH * DH + 255) / 256, 256>>>(Wn1, wt + WT_WN1, DH, DH);
    k_prep_w<<<(DH * DH + 255) / 256, 256>>>(Ws2, wt + WT_WS2, DH, DH);
    k_prep_w<<<(DH * DH + 255) / 256, 256>>>(Wn2, wt + WT_WN2, DH, DH);
    k_prep_w<<<(DH * DH + 255) / 256, 256>>>(Wp1, wt + WT_WP1, DH, DH);
    k_prep_w<<<(DH * DH + 255) / 256, 256>>>(Wp2, wt + WT_WP2, DH, DH);
    k_split_act<<<(N_NODES * (DIN / 8) + 255) / 256, 256>>>(x, xs, N_NODES, DIN);

    // CSR build
    k_zero_deg<<<(N_NODES + 255) / 256, 256>>>();
    k_count<<<(E_EDGES + 255) / 256, 256>>>(edge_dst);
    int nb = (N_NODES + 1023) / 1024;
    k_scan_block<<<nb, 1024>>>();
    k_scan_bsum<<<1, 32>>>(nb);
    k_scan_add<<<(N_NODES + 255) / 256, 256>>>();
    k_scatter<<<(E_EDGES + 255) / 256, 256>>>(edge_src, edge_dst);

    const int AGG_BLOCKS = (N_NODES * 32 + 255) / 256;
    dim3 node_grid(2, (N_NODES + 127) / 128);
    dim3 pred_grid(2, (M_PRED + 127) / 128);

    // Layer 0
    k_aggregate<DIN><<<AGG_BLOCKS, 256>>>(xs, agg);
    k_gemm_mma<<<node_grid, 256, 2 * STAGE>>>(xs, DIN, wt + WT_WS0, agg, DIN, wt + WT_WN0,
                                              b0, h1, N_NODES, 1);
    // Layer 1
    k_aggregate<DH><<<AGG_BLOCKS, 256>>>(h1, agg);
    k_gemm_mma<<<node_grid, 256, 2 * STAGE>>>(h1, DH, wt + WT_WS1, agg, DH, wt + WT_WN1,
                                              b1, h2, N_NODES, 1);
    // Layer 2 (no relu)
    k_aggregate<DH><<<AGG_BLOCKS, 256>>>(h2, agg);
    k_gemm_mma<<<node_grid, 256, 2 * STAGE>>>(h2, DH, wt + WT_WS2, agg, DH, wt + WT_WN2,
                                              b2, h3, N_NODES, 0);

    // Predictor
    k_gemm_edge_mma<<<pred_grid, 256, 2 * STAGE>>>(h3, pos_src, pos_dst, neg_src, neg_dst,
                                                   wt + WT_WP1, bp1, z1);
    k_gemm_mma<<<pred_grid, 256, 2 * STAGE>>>(z1, DH, wt + WT_WP2,
                                              (const uint8_t*)nullptr, 0, (const uint8_t*)nullptr,
                                              bp2, z2, M_PRED, 1);
    k_final<<<(M_PRED * 32 + 255) / 256, 256>>>(z2, Wp3, bp3, out);
}